// round 5
// baseline (speedup 1.0000x reference)
#include <cuda_runtime.h>

// ---------------- problem constants ----------------
#define HW      4096          // image height/width
#define OUTW    4090          // valid output size (HW - 6)
#define TPB     128           // threads per block
#define KCOLS   8             // output columns per thread
#define NC      14            // column sums per thread (KCOLS + 6 halo)
#define RROWS   32            // output rows per block strip
#define NTX     4             // column tiles: 4 * 128 * 8 = 4096 >= 4090
#define NSTRIPS 128           // ceil(4090 / 32)
#define NBLOCKS (NTX * NSTRIPS)

// SSIM constants (data_range = 2.0)
#define SSIM_C1 0.0004f            // (0.01*2)^2
#define SSIM_C2 0.0036f            // (0.03*2)^2
#define INV49   (1.0f / 49.0f)
#define CN2     (49.0f / 96.0f)    // cov_norm/2 = (49/48)/2

__device__ float g_partials[NBLOCKS];

// Load 14 consecutive columns (3x float4 + 1x float2) with precomputed,
// possibly clamped offsets. Clamped slots only feed invalid output columns.
__device__ __forceinline__ void load14(const float* __restrict__ row,
                                       int c0, int c1, int c2, int c3,
                                       float v[NC]) {
    float4 a = *reinterpret_cast<const float4*>(row + c0);
    float4 b = *reinterpret_cast<const float4*>(row + c1);
    float4 c = *reinterpret_cast<const float4*>(row + c2);
    float2 d = *reinterpret_cast<const float2*>(row + c3);
    v[0]=a.x;  v[1]=a.y;  v[2]=a.z;  v[3]=a.w;
    v[4]=b.x;  v[5]=b.y;  v[6]=b.z;  v[7]=b.w;
    v[8]=c.x;  v[9]=c.y;  v[10]=c.z; v[11]=c.w;
    v[12]=d.x; v[13]=d.y;
}

__global__ __launch_bounds__(TPB, 4)
void ssim_main(const float* __restrict__ O, const float* __restrict__ T) {
    const int base = blockIdx.x * (TPB * KCOLS) + threadIdx.x * KCOLS; // first output col
    const int y0   = blockIdx.y * RROWS;
    const int yend = min(y0 + RROWS, OUTW);

    // Column load offsets (clamped so the tail thread never reads OOB).
    const int c0 = base;                       // base <= 4088, +3 <= 4091: safe
    const int c1 = base + 4;                   // +3 <= 4095: safe
    const int c2 = min(base + 8,  HW - 4);     // clamp (only tail thread)
    const int c3 = min(base + 12, HW - 2);     // clamp (only tail thread)

    const int nvalid = min(KCOLS, OUTW - base);  // valid output cols this thread

    // Vertical sliding column sums of P=O+T, M=O-T, P^2, M^2 over 7 rows.
    float sP[NC], sM[NC], sPP[NC], sMM[NC];
    #pragma unroll
    for (int c = 0; c < NC; ++c) { sP[c] = 0.f; sM[c] = 0.f; sPP[c] = 0.f; sMM[c] = 0.f; }

    // ---- init: accumulate rows y0 .. y0+6 ----
    for (int r = 0; r < 7; ++r) {
        const float* oR = O + (y0 + r) * HW;
        const float* tR = T + (y0 + r) * HW;
        float ov[NC], tv[NC];
        load14(oR, c0, c1, c2, c3, ov);
        load14(tR, c0, c1, c2, c3, tv);
        #pragma unroll
        for (int c = 0; c < NC; ++c) {
            float P = ov[c] + tv[c];
            float M = ov[c] - tv[c];
            sP[c] += P;
            sM[c] += M;
            sPP[c] = fmaf(P, P, sPP[c]);
            sMM[c] = fmaf(M, M, sMM[c]);
        }
    }

    float acc = 0.f;

    for (int y = y0; y < yend; ++y) {
        // ---- horizontal 7-window sliding + SSIM epilogue ----
        float wP  = sP[0], wM = sM[0], wPP = sPP[0], wMM = sMM[0];
        #pragma unroll
        for (int c = 1; c < 7; ++c) {
            wP += sP[c]; wM += sM[c]; wPP += sPP[c]; wMM += sMM[c];
        }
        #pragma unroll
        for (int k = 0; k < KCOLS; ++k) {
            if (k < nvalid) {
                float p  = wP  * INV49;
                float m  = wM  * INV49;
                float qp = wPP * INV49;
                float qm = wMM * INV49;
                float p2 = p * p;
                float m2 = m * m;
                float a  = qp - p2;   // = (vx + 2*vxy + vy)/cov_norm
                float b  = qm - m2;   // = (vx - 2*vxy + vy)/cov_norm
                float A1 = fmaf(p2, 0.5f, fmaf(m2, -0.5f, SSIM_C1)); // 2*ux*uy + C1
                float B1 = fmaf(p2, 0.5f, fmaf(m2,  0.5f, SSIM_C1)); // ux^2+uy^2 + C1
                float A2 = fmaf(a, CN2, fmaf(b, -CN2, SSIM_C2));     // 2*vxy + C2
                float B2 = fmaf(a, CN2, fmaf(b,  CN2, SSIM_C2));     // vx+vy + C2
                acc += __fdividef(A1 * A2, B1 * B2);
            }
            if (k < KCOLS - 1) {
                wP  += sP[k + 7]  - sP[k];
                wM  += sM[k + 7]  - sM[k];
                wPP += sPP[k + 7] - sPP[k];
                wMM += sMM[k + 7] - sMM[k];
            }
        }

        // ---- vertical slide: add row y+7, remove row y ----
        if (y + 1 < yend) {
            const float* oN = O + (y + 7) * HW;
            const float* tN = T + (y + 7) * HW;
            const float* oO = O + y * HW;        // leaving row: L1/L2-hot reload
            const float* tO = T + y * HW;
            float onv[NC], tnv[NC], oov[NC], tov[NC];
            load14(oN, c0, c1, c2, c3, onv);
            load14(tN, c0, c1, c2, c3, tnv);
            load14(oO, c0, c1, c2, c3, oov);
            load14(tO, c0, c1, c2, c3, tov);
            #pragma unroll
            for (int c = 0; c < NC; ++c) {
                float Pn = onv[c] + tnv[c];
                float Mn = onv[c] - tnv[c];
                float Po = oov[c] + tov[c];
                float Mo = oov[c] - tov[c];
                float dP = Pn - Po;
                float dM = Mn - Mo;
                sP[c] += dP;
                sM[c] += dM;
                sPP[c] = fmaf(dP, Pn + Po, sPP[c]);  // Pn^2 - Po^2
                sMM[c] = fmaf(dM, Mn + Mo, sMM[c]);
            }
        }
    }

    // ---- deterministic block reduction ----
    #pragma unroll
    for (int o = 16; o > 0; o >>= 1)
        acc += __shfl_down_sync(0xffffffffu, acc, o);

    __shared__ float warpsum[TPB / 32];
    if ((threadIdx.x & 31) == 0) warpsum[threadIdx.x >> 5] = acc;
    __syncthreads();
    if (threadIdx.x == 0) {
        float s = 0.f;
        #pragma unroll
        for (int w = 0; w < TPB / 32; ++w) s += warpsum[w];
        g_partials[blockIdx.y * gridDim.x + blockIdx.x] = s;
    }
}

__global__ void ssim_finalize(float* __restrict__ out) {
    __shared__ double sh[256];
    double s = 0.0;
    for (int i = threadIdx.x; i < NBLOCKS; i += 256)
        s += (double)g_partials[i];
    sh[threadIdx.x] = s;
    __syncthreads();
    #pragma unroll
    for (int st = 128; st > 0; st >>= 1) {
        if (threadIdx.x < st) sh[threadIdx.x] += sh[threadIdx.x + st];
        __syncthreads();
    }
    if (threadIdx.x == 0)
        out[0] = (float)(sh[0] / ((double)OUTW * (double)OUTW));
}

extern "C" void kernel_launch(void* const* d_in, const int* in_sizes, int n_in,
                              void* d_out, int out_size) {
    (void)in_sizes; (void)n_in; (void)out_size;
    const float* O = (const float*)d_in[0];   // "output" image
    const float* T = (const float*)d_in[1];   // "target" image
    dim3 grid(NTX, NSTRIPS);
    ssim_main<<<grid, TPB>>>(O, T);
    ssim_finalize<<<1, 256>>>((float*)d_out);
}

// round 6
// speedup vs baseline: 1.0034x; 1.0034x over previous
#include <cuda_runtime.h>

// ---------------- problem constants ----------------
#define HW      4096          // image height/width
#define OUTW    4090          // valid output size (HW - 6)
#define TPB     128           // threads per block
#define KCOLS   8             // output columns per thread
#define NC      14            // column sums per thread (KCOLS + 6 halo)
#define RROWS   32            // output rows per block strip
#define NTX     4             // column tiles: 4 * 128 * 8 = 4096 >= 4090
#define NSTRIPS 128           // ceil(4090 / 32)
#define NBLOCKS (NTX * NSTRIPS)

// SSIM constants (data_range = 2.0)
#define SSIM_C1 0.0004f            // (0.01*2)^2
#define SSIM_C2 0.0036f            // (0.03*2)^2
#define INV49   (1.0f / 49.0f)
#define CN2     (49.0f / 96.0f)    // cov_norm/2 = (49/48)/2

__device__ float g_partials[NBLOCKS];

// Load 14 consecutive columns (3x float4 + 1x float2) with precomputed,
// possibly clamped offsets. Clamped slots only feed invalid output columns.
__device__ __forceinline__ void load14(const float* __restrict__ row,
                                       int c0, int c1, int c2, int c3,
                                       float v[NC]) {
    float4 a = *reinterpret_cast<const float4*>(row + c0);
    float4 b = *reinterpret_cast<const float4*>(row + c1);
    float4 c = *reinterpret_cast<const float4*>(row + c2);
    float2 d = *reinterpret_cast<const float2*>(row + c3);
    v[0]=a.x;  v[1]=a.y;  v[2]=a.z;  v[3]=a.w;
    v[4]=b.x;  v[5]=b.y;  v[6]=b.z;  v[7]=b.w;
    v[8]=c.x;  v[9]=c.y;  v[10]=c.z; v[11]=c.w;
    v[12]=d.x; v[13]=d.y;
}

__global__ __launch_bounds__(TPB, 4)
void ssim_main(const float* __restrict__ O, const float* __restrict__ T) {
    const int base = blockIdx.x * (TPB * KCOLS) + threadIdx.x * KCOLS; // first output col
    const int y0   = blockIdx.y * RROWS;
    const int yend = min(y0 + RROWS, OUTW);

    // Column load offsets (clamped so the tail thread never reads OOB).
    const int c0 = base;                       // base <= 4088, +3 <= 4091: safe
    const int c1 = base + 4;                   // +3 <= 4095: safe
    const int c2 = min(base + 8,  HW - 4);     // clamp (only tail thread)
    const int c3 = min(base + 12, HW - 2);     // clamp (only tail thread)

    const int nvalid = min(KCOLS, OUTW - base);  // valid output cols this thread

    // Vertical sliding column sums of P=O+T, M=O-T, P^2, M^2 over 7 rows.
    float sP[NC], sM[NC], sPP[NC], sMM[NC];
    #pragma unroll
    for (int c = 0; c < NC; ++c) { sP[c] = 0.f; sM[c] = 0.f; sPP[c] = 0.f; sMM[c] = 0.f; }

    // ---- init: accumulate rows y0 .. y0+6 ----
    for (int r = 0; r < 7; ++r) {
        const float* oR = O + (y0 + r) * HW;
        const float* tR = T + (y0 + r) * HW;
        float ov[NC], tv[NC];
        load14(oR, c0, c1, c2, c3, ov);
        load14(tR, c0, c1, c2, c3, tv);
        #pragma unroll
        for (int c = 0; c < NC; ++c) {
            float P = ov[c] + tv[c];
            float M = ov[c] - tv[c];
            sP[c] += P;
            sM[c] += M;
            sPP[c] = fmaf(P, P, sPP[c]);
            sMM[c] = fmaf(M, M, sMM[c]);
        }
    }

    float acc = 0.f;

    for (int y = y0; y < yend; ++y) {
        // ---- horizontal 7-window sliding + SSIM epilogue ----
        float wP  = sP[0], wM = sM[0], wPP = sPP[0], wMM = sMM[0];
        #pragma unroll
        for (int c = 1; c < 7; ++c) {
            wP += sP[c]; wM += sM[c]; wPP += sPP[c]; wMM += sMM[c];
        }
        #pragma unroll
        for (int k = 0; k < KCOLS; ++k) {
            if (k < nvalid) {
                float p  = wP  * INV49;
                float m  = wM  * INV49;
                float qp = wPP * INV49;
                float qm = wMM * INV49;
                float p2 = p * p;
                float m2 = m * m;
                float a  = qp - p2;   // = (vx + 2*vxy + vy)/cov_norm
                float b  = qm - m2;   // = (vx - 2*vxy + vy)/cov_norm
                float A1 = fmaf(p2, 0.5f, fmaf(m2, -0.5f, SSIM_C1)); // 2*ux*uy + C1
                float B1 = fmaf(p2, 0.5f, fmaf(m2,  0.5f, SSIM_C1)); // ux^2+uy^2 + C1
                float A2 = fmaf(a, CN2, fmaf(b, -CN2, SSIM_C2));     // 2*vxy + C2
                float B2 = fmaf(a, CN2, fmaf(b,  CN2, SSIM_C2));     // vx+vy + C2
                acc += __fdividef(A1 * A2, B1 * B2);
            }
            if (k < KCOLS - 1) {
                wP  += sP[k + 7]  - sP[k];
                wM  += sM[k + 7]  - sM[k];
                wPP += sPP[k + 7] - sPP[k];
                wMM += sMM[k + 7] - sMM[k];
            }
        }

        // ---- vertical slide: add row y+7, remove row y ----
        if (y + 1 < yend) {
            const float* oN = O + (y + 7) * HW;
            const float* tN = T + (y + 7) * HW;
            const float* oO = O + y * HW;        // leaving row: L1/L2-hot reload
            const float* tO = T + y * HW;
            float onv[NC], tnv[NC], oov[NC], tov[NC];
            load14(oN, c0, c1, c2, c3, onv);
            load14(tN, c0, c1, c2, c3, tnv);
            load14(oO, c0, c1, c2, c3, oov);
            load14(tO, c0, c1, c2, c3, tov);
            #pragma unroll
            for (int c = 0; c < NC; ++c) {
                float Pn = onv[c] + tnv[c];
                float Mn = onv[c] - tnv[c];
                float Po = oov[c] + tov[c];
                float Mo = oov[c] - tov[c];
                float dP = Pn - Po;
                float dM = Mn - Mo;
                sP[c] += dP;
                sM[c] += dM;
                sPP[c] = fmaf(dP, Pn + Po, sPP[c]);  // Pn^2 - Po^2
                sMM[c] = fmaf(dM, Mn + Mo, sMM[c]);
            }
        }
    }

    // ---- deterministic block reduction ----
    #pragma unroll
    for (int o = 16; o > 0; o >>= 1)
        acc += __shfl_down_sync(0xffffffffu, acc, o);

    __shared__ float warpsum[TPB / 32];
    if ((threadIdx.x & 31) == 0) warpsum[threadIdx.x >> 5] = acc;
    __syncthreads();
    if (threadIdx.x == 0) {
        float s = 0.f;
        #pragma unroll
        for (int w = 0; w < TPB / 32; ++w) s += warpsum[w];
        g_partials[blockIdx.y * gridDim.x + blockIdx.x] = s;
    }
}

__global__ void ssim_finalize(float* __restrict__ out) {
    __shared__ double sh[256];
    double s = 0.0;
    for (int i = threadIdx.x; i < NBLOCKS; i += 256)
        s += (double)g_partials[i];
    sh[threadIdx.x] = s;
    __syncthreads();
    #pragma unroll
    for (int st = 128; st > 0; st >>= 1) {
        if (threadIdx.x < st) sh[threadIdx.x] += sh[threadIdx.x + st];
        __syncthreads();
    }
    if (threadIdx.x == 0)
        out[0] = (float)(sh[0] / ((double)OUTW * (double)OUTW));
}

extern "C" void kernel_launch(void* const* d_in, const int* in_sizes, int n_in,
                              void* d_out, int out_size) {
    (void)in_sizes; (void)n_in; (void)out_size;
    const float* O = (const float*)d_in[0];   // "output" image
    const float* T = (const float*)d_in[1];   // "target" image
    dim3 grid(NTX, NSTRIPS);
    ssim_main<<<grid, TPB>>>(O, T);
    ssim_finalize<<<1, 256>>>((float*)d_out);
}

// round 7
// speedup vs baseline: 1.0220x; 1.0185x over previous
#include <cuda_runtime.h>

// ---------------- problem constants ----------------
#define HW      4096          // image height/width
#define OUTW    4090          // valid output size (HW - 6)
#define TPB     128           // threads per block
#define KCOLS   8             // output columns per thread
#define NC      14            // column sums per thread (KCOLS + 6 halo)
#define RROWS   32            // output rows per block strip
#define NTX     4             // column tiles: 4 * 128 * 8 = 4096 >= 4090
#define NSTRIPS 128           // ceil(4090 / 32)
#define NBLOCKS (NTX * NSTRIPS)

// SSIM constants (data_range = 2.0)
#define SSIM_C1 0.0004f            // (0.01*2)^2
#define SSIM_C2 0.0036f            // (0.03*2)^2
#define INV49   (1.0f / 49.0f)
#define CN2     (49.0f / 96.0f)    // cov_norm/2 = (49/48)/2

__device__ float g_partials[NBLOCKS];

// Load 14 consecutive columns (3x float4 + 1x float2) with precomputed,
// possibly clamped offsets. Clamped slots only feed invalid output columns.
__device__ __forceinline__ void load14(const float* __restrict__ row,
                                       int c0, int c1, int c2, int c3,
                                       float v[NC]) {
    float4 a = *reinterpret_cast<const float4*>(row + c0);
    float4 b = *reinterpret_cast<const float4*>(row + c1);
    float4 c = *reinterpret_cast<const float4*>(row + c2);
    float2 d = *reinterpret_cast<const float2*>(row + c3);
    v[0]=a.x;  v[1]=a.y;  v[2]=a.z;  v[3]=a.w;
    v[4]=b.x;  v[5]=b.y;  v[6]=b.z;  v[7]=b.w;
    v[8]=c.x;  v[9]=c.y;  v[10]=c.z; v[11]=c.w;
    v[12]=d.x; v[13]=d.y;
}

__global__ __launch_bounds__(TPB, 4)
void ssim_main(const float* __restrict__ O, const float* __restrict__ T) {
    const int base = blockIdx.x * (TPB * KCOLS) + threadIdx.x * KCOLS; // first output col
    const int y0   = blockIdx.y * RROWS;
    const int yend = min(y0 + RROWS, OUTW);

    // Column load offsets (clamped so the tail thread never reads OOB).
    const int c0 = base;                       // base <= 4088, +3 <= 4091: safe
    const int c1 = base + 4;                   // +3 <= 4095: safe
    const int c2 = min(base + 8,  HW - 4);     // clamp (only tail thread)
    const int c3 = min(base + 12, HW - 2);     // clamp (only tail thread)

    const int nvalid = min(KCOLS, OUTW - base);  // valid output cols this thread

    // Vertical sliding column sums of P=O+T, M=O-T, P^2, M^2 over 7 rows.
    float sP[NC], sM[NC], sPP[NC], sMM[NC];
    #pragma unroll
    for (int c = 0; c < NC; ++c) { sP[c] = 0.f; sM[c] = 0.f; sPP[c] = 0.f; sMM[c] = 0.f; }

    // ---- init: accumulate rows y0 .. y0+6 ----
    for (int r = 0; r < 7; ++r) {
        const float* oR = O + (y0 + r) * HW;
        const float* tR = T + (y0 + r) * HW;
        float ov[NC], tv[NC];
        load14(oR, c0, c1, c2, c3, ov);
        load14(tR, c0, c1, c2, c3, tv);
        #pragma unroll
        for (int c = 0; c < NC; ++c) {
            float P = ov[c] + tv[c];
            float M = ov[c] - tv[c];
            sP[c] += P;
            sM[c] += M;
            sPP[c] = fmaf(P, P, sPP[c]);
            sMM[c] = fmaf(M, M, sMM[c]);
        }
    }

    float acc = 0.f;

    for (int y = y0; y < yend; ++y) {
        // ---- horizontal 7-window sliding + SSIM epilogue ----
        float wP  = sP[0], wM = sM[0], wPP = sPP[0], wMM = sMM[0];
        #pragma unroll
        for (int c = 1; c < 7; ++c) {
            wP += sP[c]; wM += sM[c]; wPP += sPP[c]; wMM += sMM[c];
        }
        #pragma unroll
        for (int k = 0; k < KCOLS; ++k) {
            if (k < nvalid) {
                float p  = wP  * INV49;
                float m  = wM  * INV49;
                float qp = wPP * INV49;
                float qm = wMM * INV49;
                float p2 = p * p;
                float m2 = m * m;
                float a  = qp - p2;   // = (vx + 2*vxy + vy)/cov_norm
                float b  = qm - m2;   // = (vx - 2*vxy + vy)/cov_norm
                float A1 = fmaf(p2, 0.5f, fmaf(m2, -0.5f, SSIM_C1)); // 2*ux*uy + C1
                float B1 = fmaf(p2, 0.5f, fmaf(m2,  0.5f, SSIM_C1)); // ux^2+uy^2 + C1
                float A2 = fmaf(a, CN2, fmaf(b, -CN2, SSIM_C2));     // 2*vxy + C2
                float B2 = fmaf(a, CN2, fmaf(b,  CN2, SSIM_C2));     // vx+vy + C2
                acc += __fdividef(A1 * A2, B1 * B2);
            }
            if (k < KCOLS - 1) {
                wP  += sP[k + 7]  - sP[k];
                wM  += sM[k + 7]  - sM[k];
                wPP += sPP[k + 7] - sPP[k];
                wMM += sMM[k + 7] - sMM[k];
            }
        }

        // ---- vertical slide: add row y+7, remove row y ----
        if (y + 1 < yend) {
            const float* oN = O + (y + 7) * HW;
            const float* tN = T + (y + 7) * HW;
            const float* oO = O + y * HW;        // leaving row: L1/L2-hot reload
            const float* tO = T + y * HW;
            float onv[NC], tnv[NC], oov[NC], tov[NC];
            load14(oN, c0, c1, c2, c3, onv);
            load14(tN, c0, c1, c2, c3, tnv);
            load14(oO, c0, c1, c2, c3, oov);
            load14(tO, c0, c1, c2, c3, tov);
            #pragma unroll
            for (int c = 0; c < NC; ++c) {
                float Pn = onv[c] + tnv[c];
                float Mn = onv[c] - tnv[c];
                float Po = oov[c] + tov[c];
                float Mo = oov[c] - tov[c];
                float dP = Pn - Po;
                float dM = Mn - Mo;
                sP[c] += dP;
                sM[c] += dM;
                sPP[c] = fmaf(dP, Pn + Po, sPP[c]);  // Pn^2 - Po^2
                sMM[c] = fmaf(dM, Mn + Mo, sMM[c]);
            }
        }
    }

    // ---- deterministic block reduction ----
    #pragma unroll
    for (int o = 16; o > 0; o >>= 1)
        acc += __shfl_down_sync(0xffffffffu, acc, o);

    __shared__ float warpsum[TPB / 32];
    if ((threadIdx.x & 31) == 0) warpsum[threadIdx.x >> 5] = acc;
    __syncthreads();
    if (threadIdx.x == 0) {
        float s = 0.f;
        #pragma unroll
        for (int w = 0; w < TPB / 32; ++w) s += warpsum[w];
        g_partials[blockIdx.y * gridDim.x + blockIdx.x] = s;
    }
}

__global__ void ssim_finalize(float* __restrict__ out) {
    __shared__ double sh[256];
    double s = 0.0;
    for (int i = threadIdx.x; i < NBLOCKS; i += 256)
        s += (double)g_partials[i];
    sh[threadIdx.x] = s;
    __syncthreads();
    #pragma unroll
    for (int st = 128; st > 0; st >>= 1) {
        if (threadIdx.x < st) sh[threadIdx.x] += sh[threadIdx.x + st];
        __syncthreads();
    }
    if (threadIdx.x == 0)
        out[0] = (float)(sh[0] / ((double)OUTW * (double)OUTW));
}

extern "C" void kernel_launch(void* const* d_in, const int* in_sizes, int n_in,
                              void* d_out, int out_size) {
    (void)in_sizes; (void)n_in; (void)out_size;
    const float* O = (const float*)d_in[0];   // "output" image
    const float* T = (const float*)d_in[1];   // "target" image
    dim3 grid(NTX, NSTRIPS);
    ssim_main<<<grid, TPB>>>(O, T);
    ssim_finalize<<<1, 256>>>((float*)d_out);
}